// round 13
// baseline (speedup 1.0000x reference)
#include <cuda_runtime.h>
#include <cuda_bf16.h>
#include <cstdint>

#define B_  4
#define S_  4096
#define D_  1024
#define M_  (B_ * S_)          // 16384 rows
#define NPROJ 5120             // 1024(a)+1024(o)+2048(B)+1024(dt)
#define EPS 1e-6f

#define CH_ 32                 // scan chunks
#define CL_ (S_ / CH_)         // 128 steps per chunk

// ---------------- scratch (static device globals; no allocation) ------------
__device__ float  g_P[(size_t)M_ * NPROJ];          // projections (335MB)
__device__ float4 g_T[(size_t)M_ * D_];             // (a,b,u0,u1) (268MB)
__device__ __nv_bfloat16 g_xhi[(size_t)M_ * D_];
__device__ __nv_bfloat16 g_xlo[(size_t)M_ * D_];
__device__ __nv_bfloat16 g_Wthi[(size_t)NPROJ * D_];   // W^T concat, [n][k]
__device__ __nv_bfloat16 g_Wtlo[(size_t)NPROJ * D_];
__device__ __nv_bfloat16 g_WCthi[(size_t)D_ * 2 * D_]; // WC^T, [n=1024][k=2048]
__device__ __nv_bfloat16 g_WCtlo[(size_t)D_ * 2 * D_];
__device__ __nv_bfloat16 g_Hhi[(size_t)M_ * 2 * D_];   // states bf16 hi [m][2d+j]
__device__ __nv_bfloat16 g_Hlo[(size_t)M_ * 2 * D_];
__device__ float  g_biasP[NPROJ];
__device__ float4 g_CM[B_ * D_ * CH_];              // per-chunk (Mr,Mi,Er,Ei)
__device__ float2 g_HIN[B_ * D_ * CH_];             // per-chunk entry state

// ======================= PTX helpers =========================================
__device__ __forceinline__ uint32_t smem_u32(const void* p) {
    uint32_t a;
    asm("{ .reg .u64 t; cvta.to.shared.u64 t, %1; cvt.u32.u64 %0, t; }" : "=r"(a) : "l"(p));
    return a;
}
__device__ __forceinline__ void cp_async16(uint32_t s, const void* g) {
    asm volatile("cp.async.cg.shared.global [%0], [%1], 16;" :: "r"(s), "l"(g));
}
#define CP_COMMIT()  asm volatile("cp.async.commit_group;" ::: "memory")
#define CP_WAIT1()   asm volatile("cp.async.wait_group 1;" ::: "memory")
#define CP_WAIT0()   asm volatile("cp.async.wait_group 0;" ::: "memory")

__device__ __forceinline__ void ldsm_x4(uint32_t& r0, uint32_t& r1, uint32_t& r2,
                                        uint32_t& r3, uint32_t addr) {
    asm volatile("ldmatrix.sync.aligned.m8n8.x4.shared.b16 {%0,%1,%2,%3}, [%4];"
                 : "=r"(r0), "=r"(r1), "=r"(r2), "=r"(r3) : "r"(addr));
}
__device__ __forceinline__ void mma_bf16(float* c, const uint32_t* a, const uint32_t* b) {
    asm volatile(
        "mma.sync.aligned.m16n8k16.row.col.f32.bf16.bf16.f32 "
        "{%0,%1,%2,%3}, {%4,%5,%6,%7}, {%8,%9}, {%0,%1,%2,%3};"
        : "+f"(c[0]), "+f"(c[1]), "+f"(c[2]), "+f"(c[3])
        : "r"(a[0]), "r"(a[1]), "r"(a[2]), "r"(a[3]), "r"(b[0]), "r"(b[1]));
}

// ======================= bf16x3 GEMM (mma.sync, sm_100-safe) =================
// C[128 x 128] per CTA = A[128 x K] @ B^T where B is [N][K] row-major (= W^T).
// bf16 hi/lo split x3: Ahi*Bhi + Ahi*Blo + Alo*Bhi, fp32 accum.
// k-chunk 32, 2-stage cp.async pipeline, 80KB smem/CTA -> 2 CTAs per SM.
#define KC      32
#define ROWB    80                         // bytes per smem row (64 data + 16 pad)
#define TILE_BYTES (128 * ROWB)            // 10240
#define STAGE_BYTES (4 * TILE_BYTES)       // Ahi,Alo,Bhi,Blo = 40960
#define NSTAGE  2
#define GEMM_SMEM (NSTAGE * STAGE_BYTES)   // 81920

__global__ __launch_bounds__(256, 2) void gemm_bf16x3(
    const __nv_bfloat16* __restrict__ Ahi, const __nv_bfloat16* __restrict__ Alo,
    const __nv_bfloat16* __restrict__ Bhi, const __nv_bfloat16* __restrict__ Blo,
    const float* __restrict__ bias, float* __restrict__ C,
    int Kdim, int ldc)
{
    extern __shared__ char smem[];
    const uint32_t sbase = smem_u32(smem);

    const int tid  = threadIdx.x;
    const int wid  = tid >> 5;
    const int lane = tid & 31;
    const int bm   = blockIdx.y * 128;
    const int bn   = blockIdx.x * 128;
    const int wm   = (wid & 1) * 64;       // warp m offset
    const int wn   = (wid >> 1) * 32;      // warp n offset

    const size_t ldab = (size_t)Kdim * 2;  // bytes per row of A/B sources

    // cp.async: 8 chunks/thread/stage (2 per matrix). chunk c: row=c>>2, k16B=c&3
    const int c0 = tid, c1 = tid + 256;
    const int r0g = c0 >> 2, k0g = (c0 & 3) * 16;
    const int r1g = c1 >> 2, k1g = (c1 & 3) * 16;
    const uint32_t s0 = (uint32_t)(r0g * ROWB + k0g);
    const uint32_t s1 = (uint32_t)(r1g * ROWB + k1g);

    auto issue_stage = [&](int kc, int st) {
        const uint32_t sb = sbase + st * STAGE_BYTES;
        const size_t kbyte = (size_t)kc * (KC * 2);
        const size_t ga0 = (size_t)(bm + r0g) * ldab + kbyte + k0g;
        const size_t ga1 = (size_t)(bm + r1g) * ldab + kbyte + k1g;
        const size_t gb0 = (size_t)(bn + r0g) * ldab + kbyte + k0g;
        const size_t gb1 = (size_t)(bn + r1g) * ldab + kbyte + k1g;
        cp_async16(sb + s0,                  (const char*)Ahi + ga0);
        cp_async16(sb + s1,                  (const char*)Ahi + ga1);
        cp_async16(sb + TILE_BYTES + s0,     (const char*)Alo + ga0);
        cp_async16(sb + TILE_BYTES + s1,     (const char*)Alo + ga1);
        cp_async16(sb + 2 * TILE_BYTES + s0, (const char*)Bhi + gb0);
        cp_async16(sb + 2 * TILE_BYTES + s1, (const char*)Bhi + gb1);
        cp_async16(sb + 3 * TILE_BYTES + s0, (const char*)Blo + gb0);
        cp_async16(sb + 3 * TILE_BYTES + s1, (const char*)Blo + gb1);
        CP_COMMIT();
    };

    const int NC = Kdim / KC;
    issue_stage(0, 0);
    issue_stage(1, 1);

    float acc[4][4][4];
#pragma unroll
    for (int mt = 0; mt < 4; mt++)
#pragma unroll
        for (int nt = 0; nt < 4; nt++)
#pragma unroll
            for (int j = 0; j < 4; j++) acc[mt][nt][j] = 0.f;

    // ldmatrix lane offsets
    const int a_m = (lane & 7) + (lane & 8);          // row within m16 tile group
    const int a_k = (lane & 16) ? 8 : 0;              // k-half
    const int b_n = (lane & 7) + ((lane & 16) ? 8 : 0);
    const int b_k = (lane & 8) ? 8 : 0;

    for (int c = 0; c < NC; c++) {
        if (c + 1 < NC) CP_WAIT1(); else CP_WAIT0();
        __syncthreads();

        const int st = c & 1;
        const uint32_t sA_h = sbase + st * STAGE_BYTES;
        const uint32_t sA_l = sA_h + TILE_BYTES;
        const uint32_t sB_h = sA_h + 2 * TILE_BYTES;
        const uint32_t sB_l = sA_h + 3 * TILE_BYTES;

#pragma unroll
        for (int k16 = 0; k16 < KC / 16; k16++) {
            const int k0 = k16 * 16;
            uint32_t bh[4][2], bl[4][2];
#pragma unroll
            for (int np = 0; np < 2; np++) {
                uint32_t off = (uint32_t)((wn + np * 16 + b_n) * ROWB + (k0 + b_k) * 2);
                ldsm_x4(bh[2*np][0], bh[2*np][1], bh[2*np+1][0], bh[2*np+1][1], sB_h + off);
                ldsm_x4(bl[2*np][0], bl[2*np][1], bl[2*np+1][0], bl[2*np+1][1], sB_l + off);
            }
#pragma unroll
            for (int mt = 0; mt < 4; mt++) {
                uint32_t ah[4], al[4];
                uint32_t off = (uint32_t)((wm + mt * 16 + a_m) * ROWB + (k0 + a_k) * 2);
                ldsm_x4(ah[0], ah[1], ah[2], ah[3], sA_h + off);
                ldsm_x4(al[0], al[1], al[2], al[3], sA_l + off);
#pragma unroll
                for (int nt = 0; nt < 4; nt++) {
                    mma_bf16(acc[mt][nt], ah, bh[nt]);
                    mma_bf16(acc[mt][nt], ah, bl[nt]);
                    mma_bf16(acc[mt][nt], al, bh[nt]);
                }
            }
        }
        __syncthreads();
        if (c + 2 < NC) issue_stage(c + 2, st);
    }

    // epilogue
    const int er = lane >> 2;
    const int ec = (lane & 3) * 2;
#pragma unroll
    for (int mt = 0; mt < 4; mt++) {
#pragma unroll
        for (int nt = 0; nt < 4; nt++) {
            const int col = bn + wn + nt * 8 + ec;
            const float2 bv = *(const float2*)&bias[col];
            const int row0 = bm + wm + mt * 16 + er;
            float2 v0, v1;
            v0.x = acc[mt][nt][0] + bv.x;
            v0.y = acc[mt][nt][1] + bv.y;
            v1.x = acc[mt][nt][2] + bv.x;
            v1.y = acc[mt][nt][3] + bv.y;
            *(float2*)&C[(size_t)row0 * ldc + col]       = v0;
            *(float2*)&C[(size_t)(row0 + 8) * ldc + col] = v1;
        }
    }
}

// ======================= prep kernels ========================================
__device__ __forceinline__ void split_bf16(float v, __nv_bfloat16& h, __nv_bfloat16& l) {
    h = __float2bfloat16(v);
    l = __float2bfloat16(v - __bfloat162float(h));
}

__global__ __launch_bounds__(256) void k_split_x(const float* __restrict__ x) {
    size_t i4 = ((size_t)blockIdx.x * blockDim.x + threadIdx.x) * 4;
    if (i4 >= (size_t)M_ * D_) return;
    float4 v = *(const float4*)&x[i4];
    __nv_bfloat16 h0, l0, h1, l1, h2, l2, h3, l3;
    split_bf16(v.x, h0, l0); split_bf16(v.y, h1, l1);
    split_bf16(v.z, h2, l2); split_bf16(v.w, h3, l3);
    *(__nv_bfloat162*)&g_xhi[i4]     = __nv_bfloat162(h0, h1);
    *(__nv_bfloat162*)&g_xhi[i4 + 2] = __nv_bfloat162(h2, h3);
    *(__nv_bfloat162*)&g_xlo[i4]     = __nv_bfloat162(l0, l1);
    *(__nv_bfloat162*)&g_xlo[i4 + 2] = __nv_bfloat162(l2, l3);
}

// Wt_all[n][k] via 32x32 smem tile transpose (coalesced reads AND writes).
__global__ __launch_bounds__(256) void k_build_wt(
    const float* __restrict__ Wa, const float* __restrict__ Wo,
    const float* __restrict__ WB, const float* __restrict__ Wdt)
{
    __shared__ float t[32][33];
    const int bn = blockIdx.x * 32;   // output n base
    const int bk = blockIdx.y * 32;   // output k base
    const int tx = threadIdx.x & 31;
    const int ty = threadIdx.x >> 5;  // 0..7

    const float* W; int ldw, noff;
    if (bn < 1024)      { W = Wa;  ldw = 1024; noff = 0; }
    else if (bn < 2048) { W = Wo;  ldw = 1024; noff = 1024; }
    else if (bn < 4096) { W = WB;  ldw = 2048; noff = 2048; }
    else                { W = Wdt; ldw = 1024; noff = 4096; }

#pragma unroll
    for (int i = 0; i < 32; i += 8)
        t[ty + i][tx] = W[(size_t)(bk + ty + i) * ldw + (bn - noff) + tx];
    __syncthreads();
#pragma unroll
    for (int i = 0; i < 32; i += 8) {
        float v = t[tx][ty + i];
        __nv_bfloat16 h, l; split_bf16(v, h, l);
        size_t o = (size_t)(bn + ty + i) * 1024 + bk + tx;
        g_Wthi[o] = h;
        g_Wtlo[o] = l;
    }
}

__global__ __launch_bounds__(256) void k_build_wct(const float* __restrict__ WC) {
    __shared__ float t[32][33];
    const int bn = blockIdx.x * 32;
    const int bk = blockIdx.y * 32;
    const int tx = threadIdx.x & 31;
    const int ty = threadIdx.x >> 5;
#pragma unroll
    for (int i = 0; i < 32; i += 8)
        t[ty + i][tx] = WC[(size_t)(bk + ty + i) * 1024 + bn + tx];
    __syncthreads();
#pragma unroll
    for (int i = 0; i < 32; i += 8) {
        float v = t[tx][ty + i];
        __nv_bfloat16 h, l; split_bf16(v, h, l);
        size_t o = (size_t)(bn + ty + i) * 2048 + bk + tx;
        g_WCthi[o] = h;
        g_WCtlo[o] = l;
    }
}

__global__ __launch_bounds__(256) void k_build_bias(
    const float* __restrict__ ba, const float* __restrict__ bo,
    const float* __restrict__ bB, const float* __restrict__ bdt)
{
    int n = blockIdx.x * blockDim.x + threadIdx.x;
    if (n >= NPROJ) return;
    float v;
    if (n < 1024) v = ba[n];
    else if (n < 2048) v = bo[n - 1024];
    else if (n < 4096) v = bB[n - 2048];
    else v = bdt[n - 4096];
    g_biasP[n] = v;
}

// ======================= elementwise transform ===============================
__device__ __forceinline__ float softplus_f(float x) {
    return fmaxf(x, 0.f) + log1pf(expf(-fabsf(x)));
}

__device__ __forceinline__ float4 kssm_transform(float pa, float po, float2 pB,
                                                 float pdt, float xv) {
    float alpha = softplus_f(pa);
    float omega = po;
    float dt    = softplus_f(pdt);
    float tau = dt * 0.5f;
    float opa = fmaf(tau, alpha, 1.0f);
    float tw  = tau * omega;
    float inv = 1.0f / (fmaf(opa, opa, fmaf(tw, tw, EPS)));
    float m11 = opa * inv;
    float m12 = tw * inv;
    float oma = fmaf(-tau, alpha, 1.0f);
    float a = m11 * oma - m12 * tw;
    float b = m11 * tw + m12 * oma;
    float Bx0 = pB.x * xv;
    float Bx1 = pB.y * xv;
    float u0 = dt * (fmaf(m11, Bx0,  m12 * Bx1));
    float u1 = dt * (fmaf(-m12, Bx0, m11 * Bx1));
    return make_float4(a, b, u0, u1);
}

// ======================= chunked scan ========================================
// z' = c*z + u, c = a - i b, z = h1 + i h2.
// Pass 1 (FUSED with elementwise): read g_P + x, compute transform, write g_T,
// accumulate chunk (M, E).
__global__ __launch_bounds__(256) void k_scan1f(const float* __restrict__ x) {
    int gid = blockIdx.x * blockDim.x + threadIdx.x;   // 0..131071
    int lane = gid & 4095;
    int ch   = gid >> 12;
    int b = lane >> 10, d = lane & (D_ - 1);
    int m0 = b * S_ + ch * CL_;

    float Mr = 1.f, Mi = 0.f, Er = 0.f, Ei = 0.f;
#pragma unroll 2
    for (int s = 0; s < CL_; s++) {
        size_t m = (size_t)(m0 + s);
        const float* Prow = g_P + m * NPROJ;
        float pa  = Prow[d];
        float po  = Prow[1024 + d];
        float2 pB = ((const float2*)(Prow + 2048))[d];
        float pdt = Prow[4096 + d];
        float xv  = x[m * D_ + d];
        float4 t = kssm_transform(pa, po, pB, pdt, xv);
        g_T[m * D_ + d] = t;

        float er = fmaf(t.x, Er, fmaf( t.y, Ei, t.z));
        float ei = fmaf(t.x, Ei, fmaf(-t.y, Er, t.w));
        float mr = fmaf(t.x, Mr,  t.y * Mi);
        float mi = fmaf(t.x, Mi, -t.y * Mr);
        Er = er; Ei = ei; Mr = mr; Mi = mi;
    }
    g_CM[gid] = make_float4(Mr, Mi, Er, Ei);
}

__global__ __launch_bounds__(256) void k_scan2(const float* __restrict__ state,
                                               float* __restrict__ out_fs) {
    int gid = blockIdx.x * blockDim.x + threadIdx.x;   // 0..4095
    float zr = state[(size_t)gid * 2 + 0];
    float zi = state[(size_t)gid * 2 + 1];
#pragma unroll
    for (int ch = 0; ch < CH_; ch++) {
        int idx = (ch << 12) | gid;
        g_HIN[idx] = make_float2(zr, zi);
        float4 me = g_CM[idx];
        float nr = fmaf(me.x, zr, fmaf(-me.y, zi, me.z));
        float ni = fmaf(me.x, zi, fmaf( me.y, zr, me.w));
        zr = nr; zi = ni;
    }
    if (out_fs) {
        out_fs[(size_t)gid * 2 + 0] = zr;
        out_fs[(size_t)gid * 2 + 1] = zi;
    }
}

// Pass 3: each thread owns TWO adjacent d lanes -> 8B contiguous H stores
// (fixes the 50% sector efficiency of 4B-at-8B-stride writes).
__global__ __launch_bounds__(256) void k_scan3() {
    int gid = blockIdx.x * blockDim.x + threadIdx.x;   // 0..65535
    int p    = gid & 2047;          // pair index within (b, d/2)
    int ch   = gid >> 11;
    int b = p >> 9;                 // 512 pairs per b
    int d0 = (p & 511) * 2;
    int m0 = b * S_ + ch * CL_;
    int lane0 = (b << 10) | d0;

    float2 z0 = g_HIN[(ch << 12) | lane0];
    float2 z1 = g_HIN[(ch << 12) | (lane0 + 1)];
    float zr0 = z0.x, zi0 = z0.y, zr1 = z1.x, zi1 = z1.y;

#pragma unroll 2
    for (int s = 0; s < CL_; s++) {
        size_t m = (size_t)(m0 + s);
        const float4* tp = g_T + m * D_ + d0;
        float4 t0 = tp[0];
        float4 t1 = tp[1];
        float nr0 = fmaf(t0.x, zr0, fmaf( t0.y, zi0, t0.z));
        float ni0 = fmaf(t0.x, zi0, fmaf(-t0.y, zr0, t0.w));
        float nr1 = fmaf(t1.x, zr1, fmaf( t1.y, zi1, t1.z));
        float ni1 = fmaf(t1.x, zi1, fmaf(-t1.y, zr1, t1.w));
        zr0 = nr0; zi0 = ni0; zr1 = nr1; zi1 = ni1;

        size_t hoff = m * 2 * D_ + 2 * d0;   // 4 consecutive bf16
        __nv_bfloat16 h0h, h0l, h1h, h1l, h2h, h2l, h3h, h3l;
        split_bf16(zr0, h0h, h0l);
        split_bf16(zi0, h1h, h1l);
        split_bf16(zr1, h2h, h2l);
        split_bf16(zi1, h3h, h3l);
        __nv_bfloat162 hi01(h0h, h1h), hi23(h2h, h3h);
        __nv_bfloat162 lo01(h0l, h1l), lo23(h2l, h3l);
        *(uint2*)&g_Hhi[hoff] = make_uint2(*(uint32_t*)&hi01, *(uint32_t*)&hi23);
        *(uint2*)&g_Hlo[hoff] = make_uint2(*(uint32_t*)&lo01, *(uint32_t*)&lo23);
    }
}

// ======================= launcher ============================================
extern "C" void kernel_launch(void* const* d_in, const int* in_sizes, int n_in,
                              void* d_out, int out_size)
{
    const float* x     = (const float*)d_in[0];
    const float* state = (const float*)d_in[1];
    const float* Wa    = (const float*)d_in[2];
    const float* ba    = (const float*)d_in[3];
    const float* Wo    = (const float*)d_in[4];
    const float* bo    = (const float*)d_in[5];
    const float* WB    = (const float*)d_in[6];
    const float* bB    = (const float*)d_in[7];
    const float* Wdt   = (const float*)d_in[8];

    const float *WC, *bC, *bdt;
    if (in_sizes[9] == 1024) {  // ..., Wdt, bdt, WC, bC
        bdt = (const float*)d_in[9];
        WC  = (const float*)d_in[10];
        bC  = (const float*)d_in[11];
    } else {                    // ..., Wdt, WC, bC, bdt
        WC  = (const float*)d_in[9];
        bC  = (const float*)d_in[10];
        bdt = (const float*)d_in[11];
    }

    float* out = (float*)d_out;
    float* out_fs = nullptr;
    if (out_size >= (int)((size_t)M_ * D_ + (size_t)B_ * D_ * 2))
        out_fs = out + (size_t)M_ * D_;

    float *pP, *pbias;
    __nv_bfloat16 *pxh, *pxl, *pwh, *pwl, *pwch, *pwcl, *phh, *phl;
    cudaGetSymbolAddress((void**)&pP,   g_P);
    cudaGetSymbolAddress((void**)&pbias,g_biasP);
    cudaGetSymbolAddress((void**)&pxh,  g_xhi);
    cudaGetSymbolAddress((void**)&pxl,  g_xlo);
    cudaGetSymbolAddress((void**)&pwh,  g_Wthi);
    cudaGetSymbolAddress((void**)&pwl,  g_Wtlo);
    cudaGetSymbolAddress((void**)&pwch, g_WCthi);
    cudaGetSymbolAddress((void**)&pwcl, g_WCtlo);
    cudaGetSymbolAddress((void**)&phh,  g_Hhi);
    cudaGetSymbolAddress((void**)&phl,  g_Hlo);

    cudaFuncSetAttribute(gemm_bf16x3, cudaFuncAttributeMaxDynamicSharedMemorySize, GEMM_SMEM);

    dim3 blk(256);

    // prep (ordered so the proj GEMM is the 4th launch -> lands in ncu's
    // capture window, which has been sampling launch #4 all session)
    k_build_bias<<<(NPROJ + 255) / 256, blk>>>(ba, bo, bB, bdt);
    k_split_x  <<<(unsigned)(((size_t)M_ * D_ / 4 + 255) / 256), blk>>>(x);
    k_build_wt <<<dim3(NPROJ / 32, D_ / 32), blk>>>(Wa, Wo, WB, Wdt);

    // projections: [16384 x 1024] @ [1024 x 5120] -> g_P
    gemm_bf16x3<<<dim3(NPROJ / 128, M_ / 128), blk, GEMM_SMEM>>>(
        pxh, pxl, pwh, pwl, pbias, pP, D_, NPROJ);

    k_build_wct<<<dim3(D_ / 32, 2 * D_ / 32), blk>>>(WC);

    // fused elementwise + chunk scan pass 1
    k_scan1f<<<(B_ * D_ * CH_) / 256, blk>>>(x);
    k_scan2<<<(B_ * D_) / 256, blk>>>(state, out_fs);
    k_scan3<<<(B_ * D_ * CH_ / 2) / 256, blk>>>();

    // output: [16384 x 2048] @ [2048 x 1024] -> out
    gemm_bf16x3<<<dim3(D_ / 128, M_ / 128), blk, GEMM_SMEM>>>(
        phh, phl, pwch, pwcl, bC, out, 2 * D_, D_);
}